// round 1
// baseline (speedup 1.0000x reference)
#include <cuda_runtime.h>

#define BATCH 4
#define SQ    4096
#define SKV   1024
#define DE    1024
#define DC    768
#define NH    16
#define DH    64

// Scratch (allocation-free rule: __device__ globals)
__device__ float g_Q[(size_t)BATCH * SQ * DE];
__device__ float g_K[(size_t)BATCH * SKV * DE];
__device__ float g_V[(size_t)BATCH * SKV * DE];
__device__ float g_Ctx[(size_t)BATCH * SQ * DE];

// ---------------------------------------------------------------------------
// GEMM: C[M,N] = A[M,K] @ W[K,N] + bias[N]
// 128x128 tile, BK=16, 256 threads, 8x8 per thread.
// MODE 0: C=g_Q   MODE 1: C=g_K   MODE 2: C=g_V   MODE 3: A=g_Ctx, C=param
// ---------------------------------------------------------------------------
#define GBM 128
#define GBN 128
#define GBK 16
#define GTM 8
#define GTN 8

template <int MODE>
__global__ __launch_bounds__(256, 2)
void sgemm_bias(int M, int N, int K,
                const float* __restrict__ Ain,
                const float* __restrict__ W,
                const float* __restrict__ bias,
                float* __restrict__ Cout)
{
    const float* A = (MODE == 3) ? g_Ctx : Ain;
    float* C = (MODE == 0) ? g_Q : (MODE == 1) ? g_K : (MODE == 2) ? g_V : Cout;

    __shared__ __align__(16) float As[GBK][GBM + 4];  // stored transposed: As[k][m]
    __shared__ __align__(16) float Bs[GBK][GBN];

    const int tid = threadIdx.x;
    const int bx = blockIdx.x;   // N tile index
    const int by = blockIdx.y;   // M tile index

    A += (size_t)by * GBM * K;
    W += (size_t)bx * GBN;
    C += (size_t)by * GBM * N + (size_t)bx * GBN;
    const float* bptr = bias + (size_t)bx * GBN;

    const int aRow = tid >> 2;            // 0..63
    const int aCol = (tid & 3) << 2;      // 0,4,8,12
    const int bRow = tid >> 5;            // 0..7
    const int bCol = (tid & 31) << 2;     // 0..124

    const int tRow = (tid >> 4) * GTM;    // 0..120
    const int tCol = (tid & 15) * GTN;    // 0..120

    float acc[GTM][GTN] = {};
    float rM[GTM], rN[GTN];

    for (int k0 = 0; k0 < K; k0 += GBK) {
        #pragma unroll
        for (int p = 0; p < 2; p++) {
            int r = aRow + p * 64;
            float4 v = *reinterpret_cast<const float4*>(A + (size_t)r * K + k0 + aCol);
            As[aCol + 0][r] = v.x;
            As[aCol + 1][r] = v.y;
            As[aCol + 2][r] = v.z;
            As[aCol + 3][r] = v.w;
        }
        #pragma unroll
        for (int p = 0; p < 2; p++) {
            int r = bRow + p * 8;
            *reinterpret_cast<float4*>(&Bs[r][bCol]) =
                *reinterpret_cast<const float4*>(W + (size_t)(k0 + r) * N + bCol);
        }
        __syncthreads();

        #pragma unroll
        for (int k = 0; k < GBK; k++) {
            #pragma unroll
            for (int i = 0; i < GTM; i += 4)
                *reinterpret_cast<float4*>(&rM[i]) =
                    *reinterpret_cast<const float4*>(&As[k][tRow + i]);
            #pragma unroll
            for (int j = 0; j < GTN; j += 4)
                *reinterpret_cast<float4*>(&rN[j]) =
                    *reinterpret_cast<const float4*>(&Bs[k][tCol + j]);
            #pragma unroll
            for (int i = 0; i < GTM; i++)
                #pragma unroll
                for (int j = 0; j < GTN; j++)
                    acc[i][j] = fmaf(rM[i], rN[j], acc[i][j]);
        }
        __syncthreads();
    }

    #pragma unroll
    for (int i = 0; i < GTM; i++) {
        #pragma unroll
        for (int j = 0; j < GTN; j += 4) {
            float4 v;
            v.x = acc[i][j + 0] + bptr[tCol + j + 0];
            v.y = acc[i][j + 1] + bptr[tCol + j + 1];
            v.z = acc[i][j + 2] + bptr[tCol + j + 2];
            v.w = acc[i][j + 3] + bptr[tCol + j + 3];
            *reinterpret_cast<float4*>(C + (size_t)(tRow + i) * N + tCol + j) = v;
        }
    }
}

// ---------------------------------------------------------------------------
// Flash attention: one CTA per (q-tile of 64 rows, head, batch).
// 64x64 S tile, online softmax, Br=Bc=64, DH=64, 256 threads (16x16, 4x4 each).
// Smem layouts (stride 68 floats, 16B-aligned rows for float4 access):
//   QsT[d][r], KsT[d][c]  (d-major so S-GEMM reads are contiguous float4)
//   Vs [c][d]             (natural)
//   PsT[c][r]             (c-major so P-GEMM reads are contiguous float4)
// ---------------------------------------------------------------------------
#define ASTRIDE 68
#define ATT_SMEM_BYTES (4 * 64 * ASTRIDE * 4)   // 69632 B

__global__ __launch_bounds__(256)
void flash_attn()
{
    extern __shared__ __align__(16) float sm[];
    float* QsT = sm;
    float* KsT = sm + 1 * 64 * ASTRIDE;
    float* Vs  = sm + 2 * 64 * ASTRIDE;
    float* PsT = sm + 3 * 64 * ASTRIDE;

    const int tid = threadIdx.x;
    const int qb  = blockIdx.x;   // 0..63
    const int h   = blockIdx.y;   // 0..15
    const int b   = blockIdx.z;   // 0..3

    const float* Qg = g_Q   + ((size_t)b * SQ + qb * 64) * DE + h * DH;
    const float* Kg = g_K   + (size_t)b * SKV * DE + h * DH;
    const float* Vg = g_V   + (size_t)b * SKV * DE + h * DH;
    float*       Og = g_Ctx + ((size_t)b * SQ + qb * 64) * DE + h * DH;

    // Load Q tile (64x64), transpose to d-major, pre-apply 1/sqrt(64)
    #pragma unroll
    for (int p = 0; p < 4; p++) {
        int idx = tid + p * 256;
        int r = idx >> 4;
        int c = (idx & 15) << 2;
        float4 v = *reinterpret_cast<const float4*>(Qg + (size_t)r * DE + c);
        QsT[(c + 0) * ASTRIDE + r] = v.x * 0.125f;
        QsT[(c + 1) * ASTRIDE + r] = v.y * 0.125f;
        QsT[(c + 2) * ASTRIDE + r] = v.z * 0.125f;
        QsT[(c + 3) * ASTRIDE + r] = v.w * 0.125f;
    }

    const int ty = tid >> 4;
    const int tx = tid & 15;
    const int rowB = ty * 4;
    const int colB = tx * 4;

    float m[4], l[4], o[4][4];
    #pragma unroll
    for (int i = 0; i < 4; i++) {
        m[i] = -1e30f;
        l[i] = 0.0f;
        #pragma unroll
        for (int j = 0; j < 4; j++) o[i][j] = 0.0f;
    }

    for (int kv0 = 0; kv0 < SKV; kv0 += 64) {
        __syncthreads();  // prev P-GEMM (and initial Q stores) done before K/V overwrite
        #pragma unroll
        for (int p = 0; p < 4; p++) {
            int idx = tid + p * 256;
            int r = idx >> 4;
            int c = (idx & 15) << 2;
            float4 kv = *reinterpret_cast<const float4*>(Kg + (size_t)(kv0 + r) * DE + c);
            KsT[(c + 0) * ASTRIDE + r] = kv.x;
            KsT[(c + 1) * ASTRIDE + r] = kv.y;
            KsT[(c + 2) * ASTRIDE + r] = kv.z;
            KsT[(c + 3) * ASTRIDE + r] = kv.w;
            *reinterpret_cast<float4*>(&Vs[r * ASTRIDE + c]) =
                *reinterpret_cast<const float4*>(Vg + (size_t)(kv0 + r) * DE + c);
        }
        __syncthreads();

        // S = Q K^T  (4x4 per thread)
        float s[4][4] = {};
        #pragma unroll 16
        for (int d = 0; d < 64; d++) {
            float4 q4 = *reinterpret_cast<const float4*>(QsT + d * ASTRIDE + rowB);
            float4 k4 = *reinterpret_cast<const float4*>(KsT + d * ASTRIDE + colB);
            float qv[4] = {q4.x, q4.y, q4.z, q4.w};
            float kw[4] = {k4.x, k4.y, k4.z, k4.w};
            #pragma unroll
            for (int i = 0; i < 4; i++)
                #pragma unroll
                for (int j = 0; j < 4; j++)
                    s[i][j] = fmaf(qv[i], kw[j], s[i][j]);
        }

        // Online softmax: row reductions across the 16 threads of each row group
        #pragma unroll
        for (int i = 0; i < 4; i++) {
            float rm = fmaxf(fmaxf(s[i][0], s[i][1]), fmaxf(s[i][2], s[i][3]));
            rm = fmaxf(rm, __shfl_xor_sync(0xffffffffu, rm, 1));
            rm = fmaxf(rm, __shfl_xor_sync(0xffffffffu, rm, 2));
            rm = fmaxf(rm, __shfl_xor_sync(0xffffffffu, rm, 4));
            rm = fmaxf(rm, __shfl_xor_sync(0xffffffffu, rm, 8));
            float mn = fmaxf(m[i], rm);
            float corr = __expf(m[i] - mn);
            m[i] = mn;
            float rs = 0.0f;
            #pragma unroll
            for (int j = 0; j < 4; j++) {
                s[i][j] = __expf(s[i][j] - mn);
                rs += s[i][j];
            }
            rs += __shfl_xor_sync(0xffffffffu, rs, 1);
            rs += __shfl_xor_sync(0xffffffffu, rs, 2);
            rs += __shfl_xor_sync(0xffffffffu, rs, 4);
            rs += __shfl_xor_sync(0xffffffffu, rs, 8);
            l[i] = l[i] * corr + rs;
            #pragma unroll
            for (int j = 0; j < 4; j++) o[i][j] *= corr;
        }

        // Write P transposed (c-major)
        #pragma unroll
        for (int i = 0; i < 4; i++)
            #pragma unroll
            for (int j = 0; j < 4; j++)
                PsT[(colB + j) * ASTRIDE + rowB + i] = s[i][j];
        __syncthreads();

        // O += P V
        #pragma unroll 16
        for (int c = 0; c < 64; c++) {
            float4 p4 = *reinterpret_cast<const float4*>(PsT + c * ASTRIDE + rowB);
            float4 v4 = *reinterpret_cast<const float4*>(Vs  + c * ASTRIDE + colB);
            float pv[4] = {p4.x, p4.y, p4.z, p4.w};
            float vv[4] = {v4.x, v4.y, v4.z, v4.w};
            #pragma unroll
            for (int i = 0; i < 4; i++)
                #pragma unroll
                for (int j = 0; j < 4; j++)
                    o[i][j] = fmaf(pv[i], vv[j], o[i][j]);
        }
    }

    // Normalize and write ctx (head-concat layout => directly [b, sq, DE])
    #pragma unroll
    for (int i = 0; i < 4; i++) {
        float inv = 1.0f / l[i];
        float4 v;
        v.x = o[i][0] * inv;
        v.y = o[i][1] * inv;
        v.z = o[i][2] * inv;
        v.w = o[i][3] * inv;
        *reinterpret_cast<float4*>(Og + (size_t)(rowB + i) * DE + colB) = v;
    }
}

// ---------------------------------------------------------------------------
extern "C" void kernel_launch(void* const* d_in, const int* in_sizes, int n_in,
                              void* d_out, int out_size)
{
    const float* x  = (const float*)d_in[0];
    const float* y  = (const float*)d_in[1];
    const float* Wq = (const float*)d_in[2];
    const float* bq = (const float*)d_in[3];
    const float* Wk = (const float*)d_in[4];
    const float* bk = (const float*)d_in[5];
    const float* Wv = (const float*)d_in[6];
    const float* bv = (const float*)d_in[7];
    const float* Wo = (const float*)d_in[8];
    const float* bo = (const float*)d_in[9];
    float* out = (float*)d_out;

    (void)in_sizes; (void)n_in; (void)out_size;

    // Q = x @ Wq + bq : [16384,1024] x [1024,1024]
    sgemm_bias<0><<<dim3(DE / GBN, (BATCH * SQ) / GBM), 256>>>(
        BATCH * SQ, DE, DE, x, Wq, bq, nullptr);
    // K = y @ Wk + bk : [4096,768] x [768,1024]
    sgemm_bias<1><<<dim3(DE / GBN, (BATCH * SKV) / GBM), 256>>>(
        BATCH * SKV, DE, DC, y, Wk, bk, nullptr);
    // V = y @ Wv + bv
    sgemm_bias<2><<<dim3(DE / GBN, (BATCH * SKV) / GBM), 256>>>(
        BATCH * SKV, DE, DC, y, Wv, bv, nullptr);

    // Fused attention -> g_Ctx
    cudaFuncSetAttribute(flash_attn, cudaFuncAttributeMaxDynamicSharedMemorySize,
                         ATT_SMEM_BYTES);
    flash_attn<<<dim3(SQ / 64, NH, BATCH), 256, ATT_SMEM_BYTES>>>();

    // out = ctx @ Wo + bo
    sgemm_bias<3><<<dim3(DE / GBN, (BATCH * SQ) / GBM), 256>>>(
        BATCH * SQ, DE, DE, nullptr, Wo, bo, out);
}